// round 14
// baseline (speedup 1.0000x reference)
#include <cuda_runtime.h>
#include <cstdint>

typedef unsigned long long ull;

#define TT 800
#define BB 128
#define HH 256
#define AA 64
#define UU 64
#define KK 10
#define NCTA 128
#define NTHR 512
#define CHUNK 128
#define R1 323
#define R2 579
#define R3 579
#define HB (HH*BB)

// shared layout (floats), recurrent kernel
#define OFF_W1 0
#define OFF_W2 (R1*32)
#define OFF_W3 (OFF_W2 + R2*32)
#define OFF_BS (OFF_W3 + R3*32)
#define OFF_CS (OFF_BS + 96)
#define OFF_WIN (OFF_CS + 768)
#define OFF_CHR (OFF_WIN + 128)
#define OFF_XS  (OFF_CHR + 64)
#define SMEM_FLOATS (OFF_XS + CHUNK*32)
#define SMEM_BYTES (SMEM_FLOATS*4)          // 210176

#define HEADS_FLOATS (256*128)
#define HEADS_BYTES (HEADS_FLOATS*4)        // 131072

// output layout (floats)
#define OUT_ES 0
#define OUT_PI 102400
#define OUT_M1 (OUT_PI + 2048000)
#define OUT_M2 (OUT_M1 + 2048000)
#define OUT_S1 (OUT_M2 + 2048000)
#define OUT_S2 (OUT_S1 + 2048000)
#define OUT_RH (OUT_S2 + 2048000)

__device__ float g_h1[2*HB];
__device__ float g_h2[2*HB];
__device__ float g_h3[2*HB];
__device__ float g_h1T[BB*HH];          // [batch][unit] transposed copy for window
__device__ float g_w[AA*BB];            // [a][b]
__device__ float g_kappa[BB*KK];
__device__ float g_xT[TT*3*BB];         // [t][k][b]
__device__ float g_WwT[30*HH];          // [m][k]
__device__ float g_out[(size_t)TT*HH*BB]; // [t][unit][b]
__device__ unsigned g_ctr[5*32];        // group g at g*32 (monotonic), init slot 128

__device__ __forceinline__ float sig_(float x){ return 1.0f/(1.0f+__expf(-x)); }

// Release: only warps that performed global stores fence; bar.sync orders
// those fences before thread 0's arrival atomic.
__device__ __forceinline__ void bar_arrive(unsigned* ctr, int nfence){
    if (threadIdx.x < (unsigned)nfence) __threadfence();
    __syncthreads();
    if (threadIdx.x == 0) atomicAdd(ctr, 1u);
}
// Acquire side: R9-proven form — volatile spin + sync + full fence.
__device__ __forceinline__ void bar_wait(unsigned* ctr, unsigned target){
    if (threadIdx.x == 0){
        while (*(volatile unsigned*)ctr < target) { }
    }
    __syncthreads();
    __threadfence();
}

__device__ __forceinline__ ull rep2(float v){
    ull r; asm("mov.b64 %0, {%1, %1};" : "=l"(r) : "f"(v)); return r;
}
__device__ __forceinline__ void fma2(ull& acc, ull a, ull b){
    asm("fma.rn.f32x2 %0, %1, %2, %0;" : "+l"(acc) : "l"(a), "l"(b));
}
__device__ __forceinline__ ull add2(ull a, ull b){
    ull r; asm("add.rn.f32x2 %0, %1, %2;" : "=l"(r) : "l"(a), "l"(b)); return r;
}

// Per-layer row maps (cross-CTA rows in LATE chunks):
// L1: [h1self 0-255 | x 256-258 | w 259-322]
// L2: [h2self 0-255 | x 256-258 | h1new 259-514 | w 515-578]
// L3: [h3self 0-255 | x 256-258 | w 259-322 | h2new 323-578]
template<int L>
__device__ __forceinline__ float fetch_in(int r, int b, int bt32,
    const float* xrow, const float* hS, const float* hO){
    int col = bt32 + b;
    if (r < 256) return __ldcg(hS + r*BB + col);
    if (r < 259) return __ldcg(xrow + (r-256)*BB + col);
    if (L == 2){
        if (r < 515) return __ldcg(hO + (r-259)*BB + col);
        return __ldcg(g_w + (r-515)*BB + col);
    } else if (L == 3){
        if (r < 323) return __ldcg(g_w + (r-259)*BB + col);
        return __ldcg(hO + (r-323)*BB + col);
    }
    return __ldcg(g_w + (r-259)*BB + col);   // L1
}

template<int L>
__device__ __forceinline__ void prefetch8(float* rbuf, int k0, int rows,
    const float* xrow, const float* hS, const float* hO, int bt32){
    #pragma unroll
    for (int i = 0; i < 8; i++){
        int idx = threadIdx.x + i*NTHR;
        int gk = k0 + (idx >> 5), b = idx & 31;
        rbuf[i] = (gk < rows) ? fetch_in<L>(gk, b, bt32, xrow, hS, hO) : 0.f;
    }
}

// Attention window body: wait(b1), matvec h1T @ WwT, kappa update, Phi
// scatter-add, write w column, arrive(b2). All 512 threads participate.
__device__ __forceinline__ void window_inner(float* sm, const float* bw,
                                             int wb, unsigned* gctr,
                                             unsigned b1target){
    const int tid = threadIdx.x;
    float* winb = sm + OFF_WIN;
    const int* chars = (const int*)(sm + OFF_CHR);
    const int lane = tid & 31, wr = tid >> 5;

    bar_wait(gctr, b1target);   // h1T(t) produced by whole group

    if (wr < 8){
        float vr0=0.f, vr1=0.f, vr2=0.f, vr3=0.f;
        #pragma unroll
        for (int kk = 0; kk < 8; kk++){
            int k = kk*32 + lane;
            float hv = __ldcg(g_h1T + wb*HH + k);   // coalesced
            vr0 = fmaf(hv, g_WwT[(wr)    *HH + k], vr0);
            vr1 = fmaf(hv, g_WwT[(wr+8)  *HH + k], vr1);
            vr2 = fmaf(hv, g_WwT[(wr+16) *HH + k], vr2);
            if (wr < 6) vr3 = fmaf(hv, g_WwT[(wr+24)*HH + k], vr3);
        }
        #pragma unroll
        for (int off = 16; off; off >>= 1){
            vr0 += __shfl_down_sync(0xffffffffu, vr0, off);
            vr1 += __shfl_down_sync(0xffffffffu, vr1, off);
            vr2 += __shfl_down_sync(0xffffffffu, vr2, off);
            vr3 += __shfl_down_sync(0xffffffffu, vr3, off);
        }
        if (lane == 0){
            winb[wr] = vr0; winb[wr+8] = vr1; winb[wr+16] = vr2;
            if (wr < 6) winb[wr+24] = vr3;
        }
    }
    __syncthreads();
    if (tid < 30){
        float e = __expf(winb[tid] + bw[tid]);
        if (tid >= 20){
            float kap = fmaf(0.1f, e, g_kappa[wb*KK + tid - 20]);
            g_kappa[wb*KK + tid - 20] = kap;
            e = kap;
        }
        winb[32 + tid] = e;
    }
    if (tid >= 64 && tid < 128) winb[tid] = 0.f;
    __syncthreads();
    if (tid < 64){
        float fu = (float)tid;
        float s = 0.f;
        #pragma unroll
        for (int k = 0; k < KK; k++){
            float d = winb[52 + k] - fu;
            s = fmaf(winb[32 + k], __expf(-winb[42 + k]*d*d), s);
        }
        atomicAdd(winb + 64 + chars[tid], s);
    }
    __syncthreads();
    if (tid < 64) __stcg(g_w + tid*BB + wb, winb[64 + tid]);

    bar_arrive(gctr, 64);       // b2: w(t) released
}

// LSTM gate-GEMM + cell update; 32 batches x 32 gate-cols per CTA; 512 threads.
// Single-buffer staging (R9-proven). Deferred cross-CTA wait before
// prefetching chunk `wchunk`. For L==2, the attention window executes after
// chunk 0's compute (overlapping the b1 wait with chunk-0 work).
template<int L>
__device__ __forceinline__ void lstm_phase(
    float* sm, const float* Wsm, const float* bsl, float* cstl,
    int rows, const float* xrow, const float* hS, const float* hO,
    float* hOut, float* hT, float* outRow, int bt32, int ht, float* rbuf,
    unsigned* wctr, unsigned wtarget, int wchunk,
    const float* bw, int wb, unsigned b1target)
{
    const int tid = threadIdx.x;
    float* Xs = sm + OFF_XS;
    const int kg = tid >> 7;       // k-split 4
    const int gg = tid & 127;
    const int c2 = (gg & 15)*2;    // col pair
    const int b4 = (gg >> 4)*4;    // 4 batches

    ull A0=0, A1=0, A2=0, A3=0;

    for (int k0 = 0; k0 < rows; k0 += CHUNK){
        __syncthreads();
        #pragma unroll
        for (int i = 0; i < 8; i++) Xs[tid + i*NTHR] = rbuf[i];
        __syncthreads();
        if (k0 + CHUNK < rows){
            if (wchunk >= 0 && k0 == (wchunk-1)*CHUNK)
                bar_wait(wctr, wtarget);
            prefetch8<L>(rbuf, k0 + CHUNK, rows, xrow, hS, hO, bt32);
        }
        int kn = rows - k0; if (kn > CHUNK) kn = CHUNK;
        int ks, ke;
        if (kn == CHUNK){ ks = kg*32; ke = ks + 32; }
        else { ks = kg*17; if (ks > kn) ks = kn; ke = ks + 17; if (ke > kn) ke = kn; }
        const float* xp = Xs + ks*32 + b4;
        const float* wp = Wsm + (k0 + ks)*32 + c2;
        #pragma unroll 8
        for (int kk = ks; kk < ke; kk++){
            longlong2 xa = *(const longlong2*)xp;
            float2 wv = *(const float2*)wp;
            ull wx = rep2(wv.x), wy = rep2(wv.y);
            fma2(A0, (ull)xa.x, wx); fma2(A1, (ull)xa.y, wx);
            fma2(A2, (ull)xa.x, wy); fma2(A3, (ull)xa.y, wy);
            xp += 32; wp += 32;
        }
        if (L == 2 && k0 == 0)
            window_inner(sm, bw, wb, wctr, b1target);
    }
    __syncthreads();
    ull* P = (ull*)Xs;   // [kg][32 cols][16 batch-pairs]
    {
        int base = kg*512 + c2*16 + (b4 >> 1);
        P[base+0]  = A0; P[base+1]  = A1;
        P[base+16] = A2; P[base+17] = A3;
    }
    __syncthreads();
    {
        ull r = P[tid];
        r = add2(r, P[512 + tid]);
        r = add2(r, P[1024 + tid]);
        r = add2(r, P[1536 + tid]);
        P[tid] = r;
    }
    __syncthreads();
    if (tid < 256){
        const int b = tid & 31, u = tid >> 5;
        float iv = Xs[u*32 + b]       + bsl[u];
        float fv = Xs[(8+u)*32 + b]   + bsl[8+u];
        float gv = Xs[(16+u)*32 + b]  + bsl[16+u];
        float ov = Xs[(24+u)*32 + b]  + bsl[24+u];
        float ival = sig_(iv), fval = sig_(fv), gval = tanhf(gv), oval = sig_(ov);
        float cnew = fmaf(fval, cstl[tid], ival*gval);
        cstl[tid] = cnew;
        float h = oval * tanhf(cnew);
        int gidx = (ht*8 + u)*BB + bt32 + b;
        __stcg(hOut + gidx, h);
        if (hT) __stcg(hT + (bt32 + b)*HH + ht*8 + u, h);
        if (outRow) outRow[gidx] = h;
    }
}

__global__ void __launch_bounds__(NTHR, 1) recurrent_kernel(
    const float* __restrict__ x, const int* __restrict__ c,
    const float* __restrict__ Wih1, const float* __restrict__ Whh1,
    const float* __restrict__ bih1, const float* __restrict__ bhh1,
    const float* __restrict__ Wih2, const float* __restrict__ Whh2,
    const float* __restrict__ bih2, const float* __restrict__ bhh2,
    const float* __restrict__ Wih3, const float* __restrict__ Whh3,
    const float* __restrict__ bih3, const float* __restrict__ bhh3,
    const float* __restrict__ Ww, const float* __restrict__ bw)
{
    extern __shared__ float sm[];
    const int tid = threadIdx.x;
    const int bx = blockIdx.x;
    const int bt = bx >> 5, ht = bx & 31;
    const int bt32 = bt*32;

    // weight smem loads in dependency row order
    for (int idx = tid; idx < R1*32; idx += NTHR){
        int k = idx >> 5, cc = idx & 31;
        int j = (cc >> 3)*256 + ht*8 + (cc & 7);
        float v;
        if (k < 256)      v = Whh1[k*1024 + j];
        else if (k < 259) v = Wih1[(k-256)*1024 + j];
        else              v = Wih1[(3 + k-259)*1024 + j];
        sm[OFF_W1 + idx] = v;
    }
    for (int idx = tid; idx < R2*32; idx += NTHR){
        int k = idx >> 5, cc = idx & 31;
        int j = (cc >> 3)*256 + ht*8 + (cc & 7);
        float v;
        if (k < 256)      v = Whh2[k*1024 + j];
        else if (k < 259) v = Wih2[(k-256)*1024 + j];
        else if (k < 515) v = Wih2[(67 + k-259)*1024 + j];   // h1 rows
        else              v = Wih2[(3 + k-515)*1024 + j];    // w rows
        sm[OFF_W2 + idx] = v;
    }
    for (int idx = tid; idx < R3*32; idx += NTHR){
        int k = idx >> 5, cc = idx & 31;
        int j = (cc >> 3)*256 + ht*8 + (cc & 7);
        float v;
        if (k < 256)      v = Whh3[k*1024 + j];
        else if (k < 259) v = Wih3[(k-256)*1024 + j];
        else if (k < 323) v = Wih3[(3 + k-259)*1024 + j];    // w rows
        else              v = Wih3[(67 + k-323)*1024 + j];   // h2 rows
        sm[OFF_W3 + idx] = v;
    }
    if (tid < 96){
        int l = tid >> 5, cc = tid & 31;
        int j = (cc >> 3)*256 + ht*8 + (cc & 7);
        const float* bi = (l == 0) ? bih1 : ((l == 1) ? bih2 : bih3);
        const float* bh = (l == 0) ? bhh1 : ((l == 1) ? bhh2 : bhh3);
        sm[OFF_BS + tid] = bi[j] + bh[j];
    }
    for (int i = tid; i < 768; i += NTHR) sm[OFF_CS + i] = 0.f;
    if (tid < 64) ((int*)(sm + OFF_CHR))[tid] = c[bx*UU + tid];

    // global init (grid-strided)
    {
        const int gid = bx*NTHR + tid;
        for (int i = gid; i < TT*3*BB; i += NCTA*NTHR){
            int t = i / 384; int r = i - t*384; int k = r >> 7; int b = r & 127;
            g_xT[i] = x[b*(TT*3) + t*3 + k];
        }
        for (int i = gid; i < 30*HH; i += NCTA*NTHR){
            int m = i >> 8, k = i & 255;
            g_WwT[i] = Ww[k*30 + m];
        }
        for (int i = gid; i < 2*HB; i += NCTA*NTHR){
            g_h1[i] = 0.f; g_h2[i] = 0.f; g_h3[i] = 0.f;
        }
        for (int i = gid; i < BB*HH; i += NCTA*NTHR) g_h1T[i] = 0.f;
        for (int i = gid; i < AA*BB; i += NCTA*NTHR) g_w[i] = 1.0f;
        for (int i = gid; i < BB*KK; i += NCTA*NTHR) g_kappa[i] = 0.f;
    }
    bar_arrive(&g_ctr[128], NTHR);
    bar_wait(&g_ctr[128], 128u);

    unsigned* gctr = &g_ctr[bt*32];
    int rp = 0;
    const float* xrow = g_xT;
    float rbuf[8];
    prefetch8<1>(rbuf, 0, R1, xrow, g_h1, nullptr, bt32);

    // 3 barriers/step: b1 (h1 ready), b2 (w ready, arrives inside LSTM2),
    // b3 (h2 ready).
    for (int t = 0; t < TT; t++){
        const int wp = rp ^ 1;
        const unsigned base = 3u*(unsigned)t;

        lstm_phase<1>(sm, sm + OFF_W1, sm + OFF_BS, sm + OFF_CS, R1,
                      xrow, g_h1 + rp*HB, nullptr,
                      g_h1 + wp*HB, g_h1T, nullptr, bt32, ht, rbuf,
                      nullptr, 0u, -1, nullptr, 0, 0u);
        bar_arrive(gctr, 256);                               // b1 = base+1

        prefetch8<2>(rbuf, 0, R2, xrow, g_h2 + rp*HB, g_h1 + wp*HB, bt32);

        // LSTM2 with fused window: window (wait b1 -> compute -> arrive b2)
        // runs after chunk 0's compute; w-wait (b2) deferred to chunk 4.
        lstm_phase<2>(sm, sm + OFF_W2, sm + OFF_BS + 32, sm + OFF_CS + 256, R2,
                      xrow, g_h2 + rp*HB, g_h1 + wp*HB,
                      g_h2 + wp*HB, nullptr, nullptr, bt32, ht, rbuf,
                      gctr, 32u*(base+2), 4, bw, bx, 32u*(base+1));
        bar_arrive(gctr, 256);                               // b3 = base+3

        prefetch8<3>(rbuf, 0, R3, xrow, g_h3 + rp*HB, g_h2 + wp*HB, bt32);

        lstm_phase<3>(sm, sm + OFF_W3, sm + OFF_BS + 64, sm + OFF_CS + 512, R3,
                      xrow, g_h3 + rp*HB, g_h2 + wp*HB,
                      g_h3 + wp*HB, nullptr, g_out + (size_t)t*HH*BB, bt32, ht, rbuf,
                      gctr, 32u*(base+3), 2, nullptr, 0, 0u);
        // h3 stores released by next step's b1 arrival; h3(t) reads at t+1
        // occur after waits >= b1(t+1).

        rp = wp;
        xrow += 3*BB;
        if (t + 1 < TT)
            prefetch8<1>(rbuf, 0, R1, xrow, g_h1 + rp*HB, nullptr, bt32);
    }
}

__global__ void __launch_bounds__(256) heads_kernel(
    const float* __restrict__ We, const float* __restrict__ be,
    const float* __restrict__ Wpi, const float* __restrict__ bpi,
    const float* __restrict__ Wmu1, const float* __restrict__ bmu1,
    const float* __restrict__ Wmu2, const float* __restrict__ bmu2,
    const float* __restrict__ Ws1, const float* __restrict__ bs1,
    const float* __restrict__ Ws2, const float* __restrict__ bs2,
    const float* __restrict__ Wrho, const float* __restrict__ brho,
    float* __restrict__ dout)
{
    extern __shared__ float ws[];
    const int tid = threadIdx.x;
    const int t = blockIdx.x;

    for (int idx = tid; idx < 256*128; idx += 256){
        int k = idx >> 7, j = idx & 127;
        float v = 0.f;
        if (j == 0)       v = We[k];
        else if (j < 21)  v = Wpi [k*20 + j-1];
        else if (j < 41)  v = Wmu1[k*20 + j-21];
        else if (j < 61)  v = Wmu2[k*20 + j-41];
        else if (j < 81)  v = Ws1 [k*20 + j-61];
        else if (j < 101) v = Ws2 [k*20 + j-81];
        else if (j < 121) v = Wrho[k*20 + j-101];
        ws[idx] = v;
    }
    __syncthreads();

    const int bg = tid & 31, jg = tid >> 5;
    const float* hsrc = g_out + (size_t)t*HH*BB;
    float acc[64];
    #pragma unroll
    for (int i = 0; i < 64; i++) acc[i] = 0.f;

    for (int k = 0; k < 256; k++){
        float4 hv = *(const float4*)(hsrc + k*128 + bg*4);
        #pragma unroll
        for (int jj = 0; jj < 16; jj += 4){
            float4 wv = *(const float4*)(ws + k*128 + jg*16 + jj);
            acc[(jj+0)*4+0] = fmaf(hv.x, wv.x, acc[(jj+0)*4+0]);
            acc[(jj+0)*4+1] = fmaf(hv.y, wv.x, acc[(jj+0)*4+1]);
            acc[(jj+0)*4+2] = fmaf(hv.z, wv.x, acc[(jj+0)*4+2]);
            acc[(jj+0)*4+3] = fmaf(hv.w, wv.x, acc[(jj+0)*4+3]);
            acc[(jj+1)*4+0] = fmaf(hv.x, wv.y, acc[(jj+1)*4+0]);
            acc[(jj+1)*4+1] = fmaf(hv.y, wv.y, acc[(jj+1)*4+1]);
            acc[(jj+1)*4+2] = fmaf(hv.z, wv.y, acc[(jj+1)*4+2]);
            acc[(jj+1)*4+3] = fmaf(hv.w, wv.y, acc[(jj+1)*4+3]);
            acc[(jj+2)*4+0] = fmaf(hv.x, wv.z, acc[(jj+2)*4+0]);
            acc[(jj+2)*4+1] = fmaf(hv.y, wv.z, acc[(jj+2)*4+1]);
            acc[(jj+2)*4+2] = fmaf(hv.z, wv.z, acc[(jj+2)*4+2]);
            acc[(jj+2)*4+3] = fmaf(hv.w, wv.z, acc[(jj+2)*4+3]);
            acc[(jj+3)*4+0] = fmaf(hv.x, wv.w, acc[(jj+3)*4+0]);
            acc[(jj+3)*4+1] = fmaf(hv.y, wv.w, acc[(jj+3)*4+1]);
            acc[(jj+3)*4+2] = fmaf(hv.z, wv.w, acc[(jj+3)*4+2]);
            acc[(jj+3)*4+3] = fmaf(hv.w, wv.w, acc[(jj+3)*4+3]);
        }
    }
    __syncthreads();
    #pragma unroll
    for (int jj = 0; jj < 16; jj++)
        #pragma unroll
        for (int bb = 0; bb < 4; bb++)
            ws[(jg*16 + jj)*128 + bg*4 + bb] = acc[jj*4 + bb];
    __syncthreads();

    if (tid < 128){
        const int b = tid;
        const int tb = t*128 + b;
        float ve = ws[b] + be[0];
        dout[OUT_ES + tb] = 1.0f/(1.0f + __expf(ve));
        float pv[20]; float m = -1e30f;
        #pragma unroll
        for (int g = 0; g < 20; g++){
            pv[g] = ws[(1+g)*128 + b] + bpi[g];
            m = fmaxf(m, pv[g]);
        }
        float s = 0.f;
        #pragma unroll
        for (int g = 0; g < 20; g++){ pv[g] = __expf(pv[g] - m); s += pv[g]; }
        float inv = 1.0f/s;
        #pragma unroll
        for (int g = 0; g < 20; g++){
            dout[OUT_PI + tb*20 + g] = pv[g]*inv;
            dout[OUT_M1 + tb*20 + g] = ws[(21+g) *128 + b] + bmu1[g];
            dout[OUT_M2 + tb*20 + g] = ws[(41+g) *128 + b] + bmu2[g];
            dout[OUT_S1 + tb*20 + g] = __expf(ws[(61+g)*128 + b] + bs1[g]);
            dout[OUT_S2 + tb*20 + g] = __expf(ws[(81+g)*128 + b] + bs2[g]);
            dout[OUT_RH + tb*20 + g] = tanhf(ws[(101+g)*128 + b] + brho[g]);
        }
    }
}

__global__ void cleanup_kernel(){
    if (threadIdx.x < 160) g_ctr[threadIdx.x] = 0u;
}

extern "C" void kernel_launch(void* const* d_in, const int* in_sizes, int n_in,
                              void* d_out, int out_size){
    const float* x    = (const float*)d_in[0];
    const int*   c    = (const int*)  d_in[1];
    const float* Wih1 = (const float*)d_in[2];
    const float* Whh1 = (const float*)d_in[3];
    const float* bih1 = (const float*)d_in[4];
    const float* bhh1 = (const float*)d_in[5];
    const float* Wih2 = (const float*)d_in[6];
    const float* Whh2 = (const float*)d_in[7];
    const float* bih2 = (const float*)d_in[8];
    const float* bhh2 = (const float*)d_in[9];
    const float* Wih3 = (const float*)d_in[10];
    const float* Whh3 = (const float*)d_in[11];
    const float* bih3 = (const float*)d_in[12];
    const float* bhh3 = (const float*)d_in[13];
    const float* Ww   = (const float*)d_in[14];
    const float* bw   = (const float*)d_in[15];
    const float* We   = (const float*)d_in[16];
    const float* be   = (const float*)d_in[17];
    const float* Wpi  = (const float*)d_in[18];
    const float* bpi  = (const float*)d_in[19];
    const float* Wmu1 = (const float*)d_in[20];
    const float* bmu1 = (const float*)d_in[21];
    const float* Wmu2 = (const float*)d_in[22];
    const float* bmu2 = (const float*)d_in[23];
    const float* Ws1  = (const float*)d_in[24];
    const float* bs1  = (const float*)d_in[25];
    const float* Ws2  = (const float*)d_in[26];
    const float* bs2  = (const float*)d_in[27];
    const float* Wrho = (const float*)d_in[28];
    const float* brho = (const float*)d_in[29];
    float* dout = (float*)d_out;

    cudaFuncSetAttribute(recurrent_kernel,
        cudaFuncAttributeMaxDynamicSharedMemorySize, SMEM_BYTES);
    cudaFuncSetAttribute(heads_kernel,
        cudaFuncAttributeMaxDynamicSharedMemorySize, HEADS_BYTES);

    recurrent_kernel<<<NCTA, NTHR, SMEM_BYTES>>>(
        x, c, Wih1, Whh1, bih1, bhh1, Wih2, Whh2, bih2, bhh2,
        Wih3, Whh3, bih3, bhh3, Ww, bw);
    heads_kernel<<<TT, 256, HEADS_BYTES>>>(
        We, be, Wpi, bpi, Wmu1, bmu1, Wmu2, bmu2,
        Ws1, bs1, Ws2, bs2, Wrho, brho, dout);
    cleanup_kernel<<<1, 160>>>();
}

// round 15
// speedup vs baseline: 1.1218x; 1.1218x over previous
#include <cuda_runtime.h>
#include <cstdint>

typedef unsigned long long ull;

#define TT 800
#define BB 128
#define HH 256
#define AA 64
#define UU 64
#define KK 10
#define NCTA 128
#define NTHR 512
#define CHUNK 256
#define R1 323
#define R2 579
#define R3 579
#define HB (HH*BB)

// shared layout (floats), recurrent kernel
#define OFF_W1 0
#define OFF_W2 (R1*32)
#define OFF_W3 (OFF_W2 + R2*32)
#define OFF_BS (OFF_W3 + R3*32)
#define OFF_CS (OFF_BS + 96)
#define OFF_WIN (OFF_CS + 768)
#define OFF_CHR (OFF_WIN + 128)
#define OFF_XS  (OFF_CHR + 64)
#define SMEM_FLOATS (OFF_XS + CHUNK*32)
#define SMEM_BYTES (SMEM_FLOATS*4)          // 226560

#define HEADS_FLOATS (256*128)
#define HEADS_BYTES (HEADS_FLOATS*4)        // 131072

// output layout (floats)
#define OUT_ES 0
#define OUT_PI 102400
#define OUT_M1 (OUT_PI + 2048000)
#define OUT_M2 (OUT_M1 + 2048000)
#define OUT_S1 (OUT_M2 + 2048000)
#define OUT_S2 (OUT_S1 + 2048000)
#define OUT_RH (OUT_S2 + 2048000)

__device__ float g_h1[2*HB];
__device__ float g_h2[2*HB];
__device__ float g_h3[2*HB];
__device__ float g_h1T[BB*HH];          // [batch][unit] transposed copy for window
__device__ float g_w[AA*BB];            // [a][b]
__device__ float g_kappa[BB*KK];
__device__ float g_xT[TT*3*BB];         // [t][k][b]
__device__ float g_WwT[30*HH];          // [m][k]
__device__ float g_out[(size_t)TT*HH*BB]; // [t][unit][b]
__device__ unsigned g_ctr[5*32];        // group g at g*32 (monotonic), init slot 128

__device__ __forceinline__ float sig_(float x){ return 1.0f/(1.0f+__expf(-x)); }

// Release: only warps that performed global stores fence; bar.sync orders
// those fences before thread 0's arrival atomic.
__device__ __forceinline__ void bar_arrive(unsigned* ctr, int nfence){
    if (threadIdx.x < (unsigned)nfence) __threadfence();
    __syncthreads();
    if (threadIdx.x == 0) atomicAdd(ctr, 1u);
}
// Acquire side: R9-proven form — volatile spin + sync + full fence.
__device__ __forceinline__ void bar_wait(unsigned* ctr, unsigned target){
    if (threadIdx.x == 0){
        while (*(volatile unsigned*)ctr < target) { }
    }
    __syncthreads();
    __threadfence();
}

__device__ __forceinline__ ull rep2(float v){
    ull r; asm("mov.b64 %0, {%1, %1};" : "=l"(r) : "f"(v)); return r;
}
__device__ __forceinline__ void fma2(ull& acc, ull a, ull b){
    asm("fma.rn.f32x2 %0, %1, %2, %0;" : "+l"(acc) : "l"(a), "l"(b));
}
__device__ __forceinline__ ull add2(ull a, ull b){
    ull r; asm("add.rn.f32x2 %0, %1, %2;" : "=l"(r) : "l"(a), "l"(b)); return r;
}

// Per-layer row maps (cross-CTA rows in LATE chunks):
// L1: [h1self 0-255 | x 256-258 | w 259-322]
// L2: [h2self 0-255 | x 256-258 | h1new 259-514 | w 515-578]
// L3: [h3self 0-255 | x 256-258 | w 259-322 | h2new 323-578]
template<int L>
__device__ __forceinline__ float fetch_in(int r, int b, int bt32,
    const float* xrow, const float* hS, const float* hO){
    int col = bt32 + b;
    if (r < 256) return __ldcg(hS + r*BB + col);
    if (r < 259) return __ldcg(xrow + (r-256)*BB + col);
    if (L == 2){
        if (r < 515) return __ldcg(hO + (r-259)*BB + col);
        return __ldcg(g_w + (r-515)*BB + col);
    } else if (L == 3){
        if (r < 323) return __ldcg(g_w + (r-259)*BB + col);
        return __ldcg(hO + (r-323)*BB + col);
    }
    return __ldcg(g_w + (r-259)*BB + col);   // L1
}

template<int L>
__device__ __forceinline__ void prefetch16(float* rbuf, int k0, int rows,
    const float* xrow, const float* hS, const float* hO, int bt32){
    #pragma unroll
    for (int i = 0; i < 16; i++){
        int idx = threadIdx.x + i*NTHR;
        int gk = k0 + (idx >> 5), b = idx & 31;
        rbuf[i] = (gk < rows) ? fetch_in<L>(gk, b, bt32, xrow, hS, hO) : 0.f;
    }
}

// LSTM gate-GEMM + cell update; 32 batches x 32 gate-cols per CTA; 512 threads.
// Single-buffer staging, CHUNK=256 (fewer phase walls). Deferred cross-CTA
// wait before prefetching chunk `wchunk` (monotonic counter: later targets
// subsume earlier ones).
template<int L>
__device__ __forceinline__ void lstm_phase(
    float* sm, const float* Wsm, const float* bsl, float* cstl,
    int rows, const float* xrow, const float* hS, const float* hO,
    float* hOut, float* hT, float* outRow, int bt32, int ht, float* rbuf,
    unsigned* wctr, unsigned wtarget, int wchunk)
{
    const int tid = threadIdx.x;
    float* Xs = sm + OFF_XS;
    const int kg = tid >> 7;       // k-split 4
    const int gg = tid & 127;
    const int c2 = (gg & 15)*2;    // col pair
    const int b4 = (gg >> 4)*4;    // 4 batches

    ull A0=0, A1=0, A2=0, A3=0;

    for (int k0 = 0; k0 < rows; k0 += CHUNK){
        __syncthreads();
        #pragma unroll
        for (int i = 0; i < 16; i++) Xs[tid + i*NTHR] = rbuf[i];
        __syncthreads();
        if (k0 + CHUNK < rows){
            if (wchunk >= 0 && k0 == (wchunk-1)*CHUNK)
                bar_wait(wctr, wtarget);
            prefetch16<L>(rbuf, k0 + CHUNK, rows, xrow, hS, hO, bt32);
        }
        int kn = rows - k0; if (kn > CHUNK) kn = CHUNK;
        int ks, ke;
        if (kn == CHUNK){ ks = kg*64; ke = ks + 64; }
        else { ks = kg*17; if (ks > kn) ks = kn; ke = ks + 17; if (ke > kn) ke = kn; }
        const float* xp = Xs + ks*32 + b4;
        const float* wp = Wsm + (k0 + ks)*32 + c2;
        #pragma unroll 8
        for (int kk = ks; kk < ke; kk++){
            longlong2 xa = *(const longlong2*)xp;
            float2 wv = *(const float2*)wp;
            ull wx = rep2(wv.x), wy = rep2(wv.y);
            fma2(A0, (ull)xa.x, wx); fma2(A1, (ull)xa.y, wx);
            fma2(A2, (ull)xa.x, wy); fma2(A3, (ull)xa.y, wy);
            xp += 32; wp += 32;
        }
    }
    __syncthreads();
    ull* P = (ull*)Xs;   // [kg][32 cols][16 batch-pairs]
    {
        int base = kg*512 + c2*16 + (b4 >> 1);
        P[base+0]  = A0; P[base+1]  = A1;
        P[base+16] = A2; P[base+17] = A3;
    }
    __syncthreads();
    {
        ull r = P[tid];
        r = add2(r, P[512 + tid]);
        r = add2(r, P[1024 + tid]);
        r = add2(r, P[1536 + tid]);
        P[tid] = r;
    }
    __syncthreads();
    if (tid < 256){
        const int b = tid & 31, u = tid >> 5;
        float iv = Xs[u*32 + b]       + bsl[u];
        float fv = Xs[(8+u)*32 + b]   + bsl[8+u];
        float gv = Xs[(16+u)*32 + b]  + bsl[16+u];
        float ov = Xs[(24+u)*32 + b]  + bsl[24+u];
        float ival = sig_(iv), fval = sig_(fv), gval = tanhf(gv), oval = sig_(ov);
        float cnew = fmaf(fval, cstl[tid], ival*gval);
        cstl[tid] = cnew;
        float h = oval * tanhf(cnew);
        int gidx = (ht*8 + u)*BB + bt32 + b;
        __stcg(hOut + gidx, h);
        if (hT) __stcg(hT + (bt32 + b)*HH + ht*8 + u, h);
        if (outRow) outRow[gidx] = h;
    }
}

__device__ __forceinline__ void window_phase(float* sm, const float* bw,
                                             int wb,
                                             unsigned* wctr, unsigned wtarget){
    const int tid = threadIdx.x;
    float* winb = sm + OFF_WIN;
    const int* chars = (const int*)(sm + OFF_CHR);
    const int lane = tid & 31, wr = tid >> 5;

    bar_wait(wctr, wtarget);    // h1new (and h1T) produced by whole group

    if (wr < 8){
        float vr0=0.f, vr1=0.f, vr2=0.f, vr3=0.f;
        #pragma unroll
        for (int kk = 0; kk < 8; kk++){
            int k = kk*32 + lane;
            float hv = __ldcg(g_h1T + wb*HH + k);   // coalesced
            vr0 = fmaf(hv, g_WwT[(wr)    *HH + k], vr0);
            vr1 = fmaf(hv, g_WwT[(wr+8)  *HH + k], vr1);
            vr2 = fmaf(hv, g_WwT[(wr+16) *HH + k], vr2);
            if (wr < 6) vr3 = fmaf(hv, g_WwT[(wr+24)*HH + k], vr3);
        }
        #pragma unroll
        for (int off = 16; off; off >>= 1){
            vr0 += __shfl_down_sync(0xffffffffu, vr0, off);
            vr1 += __shfl_down_sync(0xffffffffu, vr1, off);
            vr2 += __shfl_down_sync(0xffffffffu, vr2, off);
            vr3 += __shfl_down_sync(0xffffffffu, vr3, off);
        }
        if (lane == 0){
            winb[wr] = vr0; winb[wr+8] = vr1; winb[wr+16] = vr2;
            if (wr < 6) winb[wr+24] = vr3;
        }
    }
    __syncthreads();
    if (tid < 30){
        float e = __expf(winb[tid] + bw[tid]);
        if (tid >= 20){
            float kap = fmaf(0.1f, e, g_kappa[wb*KK + tid - 20]);
            g_kappa[wb*KK + tid - 20] = kap;
            e = kap;
        }
        winb[32 + tid] = e;
    }
    if (tid >= 64 && tid < 128) winb[tid] = 0.f;
    __syncthreads();
    if (tid < 64){
        float fu = (float)tid;
        float s = 0.f;
        #pragma unroll
        for (int k = 0; k < KK; k++){
            float d = winb[52 + k] - fu;
            s = fmaf(winb[32 + k], __expf(-winb[42 + k]*d*d), s);
        }
        atomicAdd(winb + 64 + chars[tid], s);
    }
    __syncthreads();
    if (tid < 64) __stcg(g_w + tid*BB + wb, winb[64 + tid]);
}

__global__ void __launch_bounds__(NTHR, 1) recurrent_kernel(
    const float* __restrict__ x, const int* __restrict__ c,
    const float* __restrict__ Wih1, const float* __restrict__ Whh1,
    const float* __restrict__ bih1, const float* __restrict__ bhh1,
    const float* __restrict__ Wih2, const float* __restrict__ Whh2,
    const float* __restrict__ bih2, const float* __restrict__ bhh2,
    const float* __restrict__ Wih3, const float* __restrict__ Whh3,
    const float* __restrict__ bih3, const float* __restrict__ bhh3,
    const float* __restrict__ Ww, const float* __restrict__ bw)
{
    extern __shared__ float sm[];
    const int tid = threadIdx.x;
    const int bx = blockIdx.x;
    const int bt = bx >> 5, ht = bx & 31;
    const int bt32 = bt*32;

    // weight smem loads in dependency row order
    for (int idx = tid; idx < R1*32; idx += NTHR){
        int k = idx >> 5, cc = idx & 31;
        int j = (cc >> 3)*256 + ht*8 + (cc & 7);
        float v;
        if (k < 256)      v = Whh1[k*1024 + j];
        else if (k < 259) v = Wih1[(k-256)*1024 + j];
        else              v = Wih1[(3 + k-259)*1024 + j];
        sm[OFF_W1 + idx] = v;
    }
    for (int idx = tid; idx < R2*32; idx += NTHR){
        int k = idx >> 5, cc = idx & 31;
        int j = (cc >> 3)*256 + ht*8 + (cc & 7);
        float v;
        if (k < 256)      v = Whh2[k*1024 + j];
        else if (k < 259) v = Wih2[(k-256)*1024 + j];
        else if (k < 515) v = Wih2[(67 + k-259)*1024 + j];   // h1 rows
        else              v = Wih2[(3 + k-515)*1024 + j];    // w rows
        sm[OFF_W2 + idx] = v;
    }
    for (int idx = tid; idx < R3*32; idx += NTHR){
        int k = idx >> 5, cc = idx & 31;
        int j = (cc >> 3)*256 + ht*8 + (cc & 7);
        float v;
        if (k < 256)      v = Whh3[k*1024 + j];
        else if (k < 259) v = Wih3[(k-256)*1024 + j];
        else if (k < 323) v = Wih3[(3 + k-259)*1024 + j];    // w rows
        else              v = Wih3[(67 + k-323)*1024 + j];   // h2 rows
        sm[OFF_W3 + idx] = v;
    }
    if (tid < 96){
        int l = tid >> 5, cc = tid & 31;
        int j = (cc >> 3)*256 + ht*8 + (cc & 7);
        const float* bi = (l == 0) ? bih1 : ((l == 1) ? bih2 : bih3);
        const float* bh = (l == 0) ? bhh1 : ((l == 1) ? bhh2 : bhh3);
        sm[OFF_BS + tid] = bi[j] + bh[j];
    }
    for (int i = tid; i < 768; i += NTHR) sm[OFF_CS + i] = 0.f;
    if (tid < 64) ((int*)(sm + OFF_CHR))[tid] = c[bx*UU + tid];

    // global init (grid-strided)
    {
        const int gid = bx*NTHR + tid;
        for (int i = gid; i < TT*3*BB; i += NCTA*NTHR){
            int t = i / 384; int r = i - t*384; int k = r >> 7; int b = r & 127;
            g_xT[i] = x[b*(TT*3) + t*3 + k];
        }
        for (int i = gid; i < 30*HH; i += NCTA*NTHR){
            int m = i >> 8, k = i & 255;
            g_WwT[i] = Ww[k*30 + m];
        }
        for (int i = gid; i < 2*HB; i += NCTA*NTHR){
            g_h1[i] = 0.f; g_h2[i] = 0.f; g_h3[i] = 0.f;
        }
        for (int i = gid; i < BB*HH; i += NCTA*NTHR) g_h1T[i] = 0.f;
        for (int i = gid; i < AA*BB; i += NCTA*NTHR) g_w[i] = 1.0f;
        for (int i = gid; i < BB*KK; i += NCTA*NTHR) g_kappa[i] = 0.f;
    }
    bar_arrive(&g_ctr[128], NTHR);
    bar_wait(&g_ctr[128], 128u);

    unsigned* gctr = &g_ctr[bt*32];
    int rp = 0;
    const float* xrow = g_xT;
    float rbuf[16];
    prefetch16<1>(rbuf, 0, R1, xrow, g_h1, nullptr, bt32);

    // 3 barriers/step: b1 (h1 ready), b2 (w ready), b3 (h2 ready).
    for (int t = 0; t < TT; t++){
        const int wp = rp ^ 1;
        const unsigned base = 3u*(unsigned)t;

        lstm_phase<1>(sm, sm + OFF_W1, sm + OFF_BS, sm + OFF_CS, R1,
                      xrow, g_h1 + rp*HB, nullptr,
                      g_h1 + wp*HB, g_h1T, nullptr, bt32, ht, rbuf,
                      nullptr, 0u, -1);
        bar_arrive(gctr, 256);                               // b1 = base+1

        prefetch16<2>(rbuf, 0, R2, xrow, g_h2 + rp*HB, g_h1 + wp*HB, bt32);

        window_phase(sm, bw, bx, gctr, 32u*(base+1));
        bar_arrive(gctr, 64);                                // b2 = base+2

        // L2: chunk0 = h2self only; wait(b2) at k0==0 before chunk1 prefetch
        // (b2 >= b1 so h1new rows are covered too).
        lstm_phase<2>(sm, sm + OFF_W2, sm + OFF_BS + 32, sm + OFF_CS + 256, R2,
                      xrow, g_h2 + rp*HB, g_h1 + wp*HB,
                      g_h2 + wp*HB, nullptr, nullptr, bt32, ht, rbuf,
                      gctr, 32u*(base+2), 1);
        bar_arrive(gctr, 256);                               // b3 = base+3

        prefetch16<3>(rbuf, 0, R3, xrow, g_h3 + rp*HB, g_h2 + wp*HB, bt32);

        // L3: chunk0 = h3self only; wait(b3) at k0==0 before chunk1 prefetch
        // (covers w via b3 >= b2).
        lstm_phase<3>(sm, sm + OFF_W3, sm + OFF_BS + 64, sm + OFF_CS + 512, R3,
                      xrow, g_h3 + rp*HB, g_h2 + wp*HB,
                      g_h3 + wp*HB, nullptr, g_out + (size_t)t*HH*BB, bt32, ht, rbuf,
                      gctr, 32u*(base+3), 1);
        // h3 stores released by next step's b1 arrival; h3(t) reads at t+1
        // occur after waits >= b1(t+1).

        rp = wp;
        xrow += 3*BB;
        if (t + 1 < TT)
            prefetch16<1>(rbuf, 0, R1, xrow, g_h1 + rp*HB, nullptr, bt32);
    }
}

__global__ void __launch_bounds__(256) heads_kernel(
    const float* __restrict__ We, const float* __restrict__ be,
    const float* __restrict__ Wpi, const float* __restrict__ bpi,
    const float* __restrict__ Wmu1, const float* __restrict__ bmu1,
    const float* __restrict__ Wmu2, const float* __restrict__ bmu2,
    const float* __restrict__ Ws1, const float* __restrict__ bs1,
    const float* __restrict__ Ws2, const float* __restrict__ bs2,
    const float* __restrict__ Wrho, const float* __restrict__ brho,
    float* __restrict__ dout)
{
    extern __shared__ float ws[];
    const int tid = threadIdx.x;
    const int t = blockIdx.x;

    for (int idx = tid; idx < 256*128; idx += 256){
        int k = idx >> 7, j = idx & 127;
        float v = 0.f;
        if (j == 0)       v = We[k];
        else if (j < 21)  v = Wpi [k*20 + j-1];
        else if (j < 41)  v = Wmu1[k*20 + j-21];
        else if (j < 61)  v = Wmu2[k*20 + j-41];
        else if (j < 81)  v = Ws1 [k*20 + j-61];
        else if (j < 101) v = Ws2 [k*20 + j-81];
        else if (j < 121) v = Wrho[k*20 + j-101];
        ws[idx] = v;
    }
    __syncthreads();

    const int bg = tid & 31, jg = tid >> 5;
    const float* hsrc = g_out + (size_t)t*HH*BB;
    float acc[64];
    #pragma unroll
    for (int i = 0; i < 64; i++) acc[i] = 0.f;

    for (int k = 0; k < 256; k++){
        float4 hv = *(const float4*)(hsrc + k*128 + bg*4);
        #pragma unroll
        for (int jj = 0; jj < 16; jj += 4){
            float4 wv = *(const float4*)(ws + k*128 + jg*16 + jj);
            acc[(jj+0)*4+0] = fmaf(hv.x, wv.x, acc[(jj+0)*4+0]);
            acc[(jj+0)*4+1] = fmaf(hv.y, wv.x, acc[(jj+0)*4+1]);
            acc[(jj+0)*4+2] = fmaf(hv.z, wv.x, acc[(jj+0)*4+2]);
            acc[(jj+0)*4+3] = fmaf(hv.w, wv.x, acc[(jj+0)*4+3]);
            acc[(jj+1)*4+0] = fmaf(hv.x, wv.y, acc[(jj+1)*4+0]);
            acc[(jj+1)*4+1] = fmaf(hv.y, wv.y, acc[(jj+1)*4+1]);
            acc[(jj+1)*4+2] = fmaf(hv.z, wv.y, acc[(jj+1)*4+2]);
            acc[(jj+1)*4+3] = fmaf(hv.w, wv.y, acc[(jj+1)*4+3]);
            acc[(jj+2)*4+0] = fmaf(hv.x, wv.z, acc[(jj+2)*4+0]);
            acc[(jj+2)*4+1] = fmaf(hv.y, wv.z, acc[(jj+2)*4+1]);
            acc[(jj+2)*4+2] = fmaf(hv.z, wv.z, acc[(jj+2)*4+2]);
            acc[(jj+2)*4+3] = fmaf(hv.w, wv.z, acc[(jj+2)*4+3]);
            acc[(jj+3)*4+0] = fmaf(hv.x, wv.w, acc[(jj+3)*4+0]);
            acc[(jj+3)*4+1] = fmaf(hv.y, wv.w, acc[(jj+3)*4+1]);
            acc[(jj+3)*4+2] = fmaf(hv.z, wv.w, acc[(jj+3)*4+2]);
            acc[(jj+3)*4+3] = fmaf(hv.w, wv.w, acc[(jj+3)*4+3]);
        }
    }
    __syncthreads();
    #pragma unroll
    for (int jj = 0; jj < 16; jj++)
        #pragma unroll
        for (int bb = 0; bb < 4; bb++)
            ws[(jg*16 + jj)*128 + bg*4 + bb] = acc[jj*4 + bb];
    __syncthreads();

    if (tid < 128){
        const int b = tid;
        const int tb = t*128 + b;
        float ve = ws[b] + be[0];
        dout[OUT_ES + tb] = 1.0f/(1.0f + __expf(ve));
        float pv[20]; float m = -1e30f;
        #pragma unroll
        for (int g = 0; g < 20; g++){
            pv[g] = ws[(1+g)*128 + b] + bpi[g];
            m = fmaxf(m, pv[g]);
        }
        float s = 0.f;
        #pragma unroll
        for (int g = 0; g < 20; g++){ pv[g] = __expf(pv[g] - m); s += pv[g]; }
        float inv = 1.0f/s;
        #pragma unroll
        for (int g = 0; g < 20; g++){
            dout[OUT_PI + tb*20 + g] = pv[g]*inv;
            dout[OUT_M1 + tb*20 + g] = ws[(21+g) *128 + b] + bmu1[g];
            dout[OUT_M2 + tb*20 + g] = ws[(41+g) *128 + b] + bmu2[g];
            dout[OUT_S1 + tb*20 + g] = __expf(ws[(61+g)*128 + b] + bs1[g]);
            dout[OUT_S2 + tb*20 + g] = __expf(ws[(81+g)*128 + b] + bs2[g]);
            dout[OUT_RH + tb*20 + g] = tanhf(ws[(101+g)*128 + b] + brho[g]);
        }
    }
}

__global__ void cleanup_kernel(){
    if (threadIdx.x < 160) g_ctr[threadIdx.x] = 0u;
}

extern "C" void kernel_launch(void* const* d_in, const int* in_sizes, int n_in,
                              void* d_out, int out_size){
    const float* x    = (const float*)d_in[0];
    const int*   c    = (const int*)  d_in[1];
    const float* Wih1 = (const float*)d_in[2];
    const float* Whh1 = (const float*)d_in[3];
    const float* bih1 = (const float*)d_in[4];
    const float* bhh1 = (const float*)d_in[5];
    const float* Wih2 = (const float*)d_in[6];
    const float* Whh2 = (const float*)d_in[7];
    const float* bih2 = (const float*)d_in[8];
    const float* bhh2 = (const float*)d_in[9];
    const float* Wih3 = (const float*)d_in[10];
    const float* Whh3 = (const float*)d_in[11];
    const float* bih3 = (const float*)d_in[12];
    const float* bhh3 = (const float*)d_in[13];
    const float* Ww   = (const float*)d_in[14];
    const float* bw   = (const float*)d_in[15];
    const float* We   = (const float*)d_in[16];
    const float* be   = (const float*)d_in[17];
    const float* Wpi  = (const float*)d_in[18];
    const float* bpi  = (const float*)d_in[19];
    const float* Wmu1 = (const float*)d_in[20];
    const float* bmu1 = (const float*)d_in[21];
    const float* Wmu2 = (const float*)d_in[22];
    const float* bmu2 = (const float*)d_in[23];
    const float* Ws1  = (const float*)d_in[24];
    const float* bs1  = (const float*)d_in[25];
    const float* Ws2  = (const float*)d_in[26];
    const float* bs2  = (const float*)d_in[27];
    const float* Wrho = (const float*)d_in[28];
    const float* brho = (const float*)d_in[29];
    float* dout = (float*)d_out;

    cudaFuncSetAttribute(recurrent_kernel,
        cudaFuncAttributeMaxDynamicSharedMemorySize, SMEM_BYTES);
    cudaFuncSetAttribute(heads_kernel,
        cudaFuncAttributeMaxDynamicSharedMemorySize, HEADS_BYTES);

    recurrent_kernel<<<NCTA, NTHR, SMEM_BYTES>>>(
        x, c, Wih1, Whh1, bih1, bhh1, Wih2, Whh2, bih2, bhh2,
        Wih3, Whh3, bih3, bhh3, Ww, bw);
    heads_kernel<<<TT, 256, HEADS_BYTES>>>(
        We, be, Wpi, bpi, Wmu1, bmu1, Wmu2, bmu2,
        Ws1, bs1, Ws2, bs2, Wrho, brho, dout);
    cleanup_kernel<<<1, 160>>>();
}

// round 16
// speedup vs baseline: 1.2894x; 1.1494x over previous
#include <cuda_runtime.h>
#include <cstdint>

typedef unsigned long long ull;

#define TT 800
#define BB 128
#define HH 256
#define AA 64
#define UU 64
#define KK 10
#define NCTA 128
#define NTHR 512
#define CHUNK 256
#define R1 323
#define R2 579
#define R3 579
#define HB (HH*BB)

// shared layout (floats), recurrent kernel
#define OFF_W1 0
#define OFF_W2 (R1*32)
#define OFF_W3 (OFF_W2 + R2*32)
#define OFF_BS (OFF_W3 + R3*32)
#define OFF_CS (OFF_BS + 96)
#define OFF_WIN (OFF_CS + 768)
#define OFF_CHR (OFF_WIN + 128)
#define OFF_XS  (OFF_CHR + 64)
#define SMEM_FLOATS (OFF_XS + CHUNK*32)
#define SMEM_BYTES (SMEM_FLOATS*4)          // 226560

#define HEADS_FLOATS (256*128)
#define HEADS_BYTES (HEADS_FLOATS*4)        // 131072

// output layout (floats)
#define OUT_ES 0
#define OUT_PI 102400
#define OUT_M1 (OUT_PI + 2048000)
#define OUT_M2 (OUT_M1 + 2048000)
#define OUT_S1 (OUT_M2 + 2048000)
#define OUT_S2 (OUT_S1 + 2048000)
#define OUT_RH (OUT_S2 + 2048000)

__device__ float g_h1[2*HB];
__device__ float g_h2[2*HB];
__device__ float g_h3[2*HB];
__device__ float g_h1T[BB*HH];          // [batch][unit] transposed copy for window
__device__ float g_w[AA*BB];            // [a][b]
__device__ float g_kappa[BB*KK];
__device__ float g_xT[TT*3*BB];         // [t][k][b]
__device__ float g_WwT[30*HH];          // [m][k]
__device__ float g_out[(size_t)TT*HH*BB]; // [t][unit][b]
__device__ unsigned g_ctr[5*32];        // group g at g*32 (monotonic), init slot 128

__device__ __forceinline__ float sig_(float x){ return 1.0f/(1.0f+__expf(-x)); }

// Release: only warps that performed global stores fence; bar.sync orders
// those fences before thread 0's arrival atomic.
__device__ __forceinline__ void bar_arrive(unsigned* ctr, int nfence){
    if (threadIdx.x < (unsigned)nfence) __threadfence();
    __syncthreads();
    if (threadIdx.x == 0) atomicAdd(ctr, 1u);
}
// Acquire side: R9-proven form — volatile spin + sync + full fence.
__device__ __forceinline__ void bar_wait(unsigned* ctr, unsigned target){
    if (threadIdx.x == 0){
        while (*(volatile unsigned*)ctr < target) { }
    }
    __syncthreads();
    __threadfence();
}

__device__ __forceinline__ ull rep2(float v){
    ull r; asm("mov.b64 %0, {%1, %1};" : "=l"(r) : "f"(v)); return r;
}
__device__ __forceinline__ void fma2(ull& acc, ull a, ull b){
    asm("fma.rn.f32x2 %0, %1, %2, %0;" : "+l"(acc) : "l"(a), "l"(b));
}
__device__ __forceinline__ ull add2(ull a, ull b){
    ull r; asm("add.rn.f32x2 %0, %1, %2;" : "=l"(r) : "l"(a), "l"(b)); return r;
}

// Per-layer row maps (cross-CTA rows in LATE chunks):
// L1: [h1self 0-255 | x 256-258 | w 259-322]
// L2: [h2self 0-255 | x 256-258 | h1new 259-514 | w 515-578]
// L3: [h3self 0-255 | x 256-258 | w 259-322 | h2new 323-578]
template<int L>
__device__ __forceinline__ float fetch_in(int r, int b, int bt32,
    const float* xrow, const float* hS, const float* hO){
    int col = bt32 + b;
    if (r < 256) return __ldcg(hS + r*BB + col);
    if (r < 259) return __ldcg(xrow + (r-256)*BB + col);
    if (L == 2){
        if (r < 515) return __ldcg(hO + (r-259)*BB + col);
        return __ldcg(g_w + (r-515)*BB + col);
    } else if (L == 3){
        if (r < 323) return __ldcg(g_w + (r-259)*BB + col);
        return __ldcg(hO + (r-323)*BB + col);
    }
    return __ldcg(g_w + (r-259)*BB + col);   // L1
}

template<int L>
__device__ __forceinline__ void prefetch16(float* rbuf, int k0, int rows,
    const float* xrow, const float* hS, const float* hO, int bt32){
    #pragma unroll
    for (int i = 0; i < 16; i++){
        int idx = threadIdx.x + i*NTHR;
        int gk = k0 + (idx >> 5), b = idx & 31;
        rbuf[i] = (gk < rows) ? fetch_in<L>(gk, b, bt32, xrow, hS, hO) : 0.f;
    }
}

// LSTM gate-GEMM + cell update; 32 batches x 32 gate-cols per CTA; 512 threads.
// Thread tile 4 cols x 4 batches, k-split 8. Single-buffer staging, CHUNK=256.
// Deferred cross-CTA wait before prefetching chunk `wchunk`.
template<int L>
__device__ __forceinline__ void lstm_phase(
    float* sm, const float* Wsm, const float* bsl, float* cstl,
    int rows, const float* xrow, const float* hS, const float* hO,
    float* hOut, float* hT, float* outRow, int bt32, int ht, float* rbuf,
    unsigned* wctr, unsigned wtarget, int wchunk)
{
    const int tid = threadIdx.x;
    float* Xs = sm + OFF_XS;
    const int kg = tid >> 6;        // k-split 8
    const int g6 = tid & 63;
    const int c4 = (g6 >> 3)*4;     // 4 cols
    const int b4 = (g6 & 7)*4;      // 4 batches

    ull A[8];                        // [col 0..3][batch-pair 0..1]
    #pragma unroll
    for (int i = 0; i < 8; i++) A[i] = 0;

    for (int k0 = 0; k0 < rows; k0 += CHUNK){
        __syncthreads();
        #pragma unroll
        for (int i = 0; i < 16; i++) Xs[tid + i*NTHR] = rbuf[i];
        __syncthreads();
        if (k0 + CHUNK < rows){
            if (wchunk >= 0 && k0 == (wchunk-1)*CHUNK)
                bar_wait(wctr, wtarget);
            prefetch16<L>(rbuf, k0 + CHUNK, rows, xrow, hS, hO, bt32);
        }
        int kn = rows - k0; if (kn > CHUNK) kn = CHUNK;
        int ks, ke;
        if (kn == CHUNK){ ks = kg*32; ke = ks + 32; }
        else { ks = kg*9; if (ks > kn) ks = kn; ke = ks + 9; if (ke > kn) ke = kn; }
        const float* xp = Xs + ks*32 + b4;
        const float* wp = Wsm + (k0 + ks)*32 + c4;
        #pragma unroll 8
        for (int kk = ks; kk < ke; kk++){
            longlong2 xa = *(const longlong2*)xp;       // 4 batches (2 pairs)
            float4 wq = *(const float4*)wp;             // 4 cols
            ull w0 = rep2(wq.x), w1 = rep2(wq.y), w2 = rep2(wq.z), w3 = rep2(wq.w);
            fma2(A[0], (ull)xa.x, w0); fma2(A[1], (ull)xa.y, w0);
            fma2(A[2], (ull)xa.x, w1); fma2(A[3], (ull)xa.y, w1);
            fma2(A[4], (ull)xa.x, w2); fma2(A[5], (ull)xa.y, w2);
            fma2(A[6], (ull)xa.x, w3); fma2(A[7], (ull)xa.y, w3);
            xp += 32; wp += 32;
        }
    }
    __syncthreads();
    ull* P = (ull*)Xs;   // [kg 0..7][32 cols][16 batch-pairs] = 32KB
    {
        #pragma unroll
        for (int cc = 0; cc < 4; cc++){
            int base = kg*512 + (c4 + cc)*16 + (b4 >> 1);
            P[base]     = A[cc*2];
            P[base + 1] = A[cc*2 + 1];
        }
    }
    __syncthreads();
    {
        ull r = P[tid];
        #pragma unroll
        for (int j = 1; j < 8; j++) r = add2(r, P[j*512 + tid]);
        P[tid] = r;
    }
    __syncthreads();
    if (tid < 256){
        const int b = tid & 31, u = tid >> 5;
        float iv = Xs[u*32 + b]       + bsl[u];
        float fv = Xs[(8+u)*32 + b]   + bsl[8+u];
        float gv = Xs[(16+u)*32 + b]  + bsl[16+u];
        float ov = Xs[(24+u)*32 + b]  + bsl[24+u];
        float ival = sig_(iv), fval = sig_(fv), gval = tanhf(gv), oval = sig_(ov);
        float cnew = fmaf(fval, cstl[tid], ival*gval);
        cstl[tid] = cnew;
        float h = oval * tanhf(cnew);
        int gidx = (ht*8 + u)*BB + bt32 + b;
        __stcg(hOut + gidx, h);
        if (hT) __stcg(hT + (bt32 + b)*HH + ht*8 + u, h);
        if (outRow) outRow[gidx] = h;
    }
}

__device__ __forceinline__ void window_phase(float* sm, const float* bw,
                                             int wb,
                                             unsigned* wctr, unsigned wtarget){
    const int tid = threadIdx.x;
    float* winb = sm + OFF_WIN;
    const int* chars = (const int*)(sm + OFF_CHR);
    const int lane = tid & 31, wr = tid >> 5;

    bar_wait(wctr, wtarget);    // h1new (and h1T) produced by whole group

    if (wr < 8){
        float vr0=0.f, vr1=0.f, vr2=0.f, vr3=0.f;
        #pragma unroll
        for (int kk = 0; kk < 8; kk++){
            int k = kk*32 + lane;
            float hv = __ldcg(g_h1T + wb*HH + k);   // coalesced
            vr0 = fmaf(hv, g_WwT[(wr)    *HH + k], vr0);
            vr1 = fmaf(hv, g_WwT[(wr+8)  *HH + k], vr1);
            vr2 = fmaf(hv, g_WwT[(wr+16) *HH + k], vr2);
            if (wr < 6) vr3 = fmaf(hv, g_WwT[(wr+24)*HH + k], vr3);
        }
        #pragma unroll
        for (int off = 16; off; off >>= 1){
            vr0 += __shfl_down_sync(0xffffffffu, vr0, off);
            vr1 += __shfl_down_sync(0xffffffffu, vr1, off);
            vr2 += __shfl_down_sync(0xffffffffu, vr2, off);
            vr3 += __shfl_down_sync(0xffffffffu, vr3, off);
        }
        if (lane == 0){
            winb[wr] = vr0; winb[wr+8] = vr1; winb[wr+16] = vr2;
            if (wr < 6) winb[wr+24] = vr3;
        }
    }
    __syncthreads();
    if (tid < 30){
        float e = __expf(winb[tid] + bw[tid]);
        if (tid >= 20){
            float kap = fmaf(0.1f, e, g_kappa[wb*KK + tid - 20]);
            g_kappa[wb*KK + tid - 20] = kap;
            e = kap;
        }
        winb[32 + tid] = e;
    }
    if (tid >= 64 && tid < 128) winb[tid] = 0.f;
    __syncthreads();
    if (tid < 64){
        float fu = (float)tid;
        float s = 0.f;
        #pragma unroll
        for (int k = 0; k < KK; k++){
            float d = winb[52 + k] - fu;
            s = fmaf(winb[32 + k], __expf(-winb[42 + k]*d*d), s);
        }
        atomicAdd(winb + 64 + chars[tid], s);
    }
    __syncthreads();
    if (tid < 64) __stcg(g_w + tid*BB + wb, winb[64 + tid]);
}

__global__ void __launch_bounds__(NTHR, 1) recurrent_kernel(
    const float* __restrict__ x, const int* __restrict__ c,
    const float* __restrict__ Wih1, const float* __restrict__ Whh1,
    const float* __restrict__ bih1, const float* __restrict__ bhh1,
    const float* __restrict__ Wih2, const float* __restrict__ Whh2,
    const float* __restrict__ bih2, const float* __restrict__ bhh2,
    const float* __restrict__ Wih3, const float* __restrict__ Whh3,
    const float* __restrict__ bih3, const float* __restrict__ bhh3,
    const float* __restrict__ Ww, const float* __restrict__ bw)
{
    extern __shared__ float sm[];
    const int tid = threadIdx.x;
    const int bx = blockIdx.x;
    const int bt = bx >> 5, ht = bx & 31;
    const int bt32 = bt*32;

    // weight smem loads in dependency row order
    for (int idx = tid; idx < R1*32; idx += NTHR){
        int k = idx >> 5, cc = idx & 31;
        int j = (cc >> 3)*256 + ht*8 + (cc & 7);
        float v;
        if (k < 256)      v = Whh1[k*1024 + j];
        else if (k < 259) v = Wih1[(k-256)*1024 + j];
        else              v = Wih1[(3 + k-259)*1024 + j];
        sm[OFF_W1 + idx] = v;
    }
    for (int idx = tid; idx < R2*32; idx += NTHR){
        int k = idx >> 5, cc = idx & 31;
        int j = (cc >> 3)*256 + ht*8 + (cc & 7);
        float v;
        if (k < 256)      v = Whh2[k*1024 + j];
        else if (k < 259) v = Wih2[(k-256)*1024 + j];
        else if (k < 515) v = Wih2[(67 + k-259)*1024 + j];   // h1 rows
        else              v = Wih2[(3 + k-515)*1024 + j];    // w rows
        sm[OFF_W2 + idx] = v;
    }
    for (int idx = tid; idx < R3*32; idx += NTHR){
        int k = idx >> 5, cc = idx & 31;
        int j = (cc >> 3)*256 + ht*8 + (cc & 7);
        float v;
        if (k < 256)      v = Whh3[k*1024 + j];
        else if (k < 259) v = Wih3[(k-256)*1024 + j];
        else if (k < 323) v = Wih3[(3 + k-259)*1024 + j];    // w rows
        else              v = Wih3[(67 + k-323)*1024 + j];   // h2 rows
        sm[OFF_W3 + idx] = v;
    }
    if (tid < 96){
        int l = tid >> 5, cc = tid & 31;
        int j = (cc >> 3)*256 + ht*8 + (cc & 7);
        const float* bi = (l == 0) ? bih1 : ((l == 1) ? bih2 : bih3);
        const float* bh = (l == 0) ? bhh1 : ((l == 1) ? bhh2 : bhh3);
        sm[OFF_BS + tid] = bi[j] + bh[j];
    }
    for (int i = tid; i < 768; i += NTHR) sm[OFF_CS + i] = 0.f;
    if (tid < 64) ((int*)(sm + OFF_CHR))[tid] = c[bx*UU + tid];

    // global init (grid-strided)
    {
        const int gid = bx*NTHR + tid;
        for (int i = gid; i < TT*3*BB; i += NCTA*NTHR){
            int t = i / 384; int r = i - t*384; int k = r >> 7; int b = r & 127;
            g_xT[i] = x[b*(TT*3) + t*3 + k];
        }
        for (int i = gid; i < 30*HH; i += NCTA*NTHR){
            int m = i >> 8, k = i & 255;
            g_WwT[i] = Ww[k*30 + m];
        }
        for (int i = gid; i < 2*HB; i += NCTA*NTHR){
            g_h1[i] = 0.f; g_h2[i] = 0.f; g_h3[i] = 0.f;
        }
        for (int i = gid; i < BB*HH; i += NCTA*NTHR) g_h1T[i] = 0.f;
        for (int i = gid; i < AA*BB; i += NCTA*NTHR) g_w[i] = 1.0f;
        for (int i = gid; i < BB*KK; i += NCTA*NTHR) g_kappa[i] = 0.f;
    }
    bar_arrive(&g_ctr[128], NTHR);
    bar_wait(&g_ctr[128], 128u);

    unsigned* gctr = &g_ctr[bt*32];
    int rp = 0;
    const float* xrow = g_xT;
    float rbuf[16];
    prefetch16<1>(rbuf, 0, R1, xrow, g_h1, nullptr, bt32);

    // 3 barriers/step: b1 (h1 ready), b2 (w ready), b3 (h2 ready).
    for (int t = 0; t < TT; t++){
        const int wp = rp ^ 1;
        const unsigned base = 3u*(unsigned)t;

        lstm_phase<1>(sm, sm + OFF_W1, sm + OFF_BS, sm + OFF_CS, R1,
                      xrow, g_h1 + rp*HB, nullptr,
                      g_h1 + wp*HB, g_h1T, nullptr, bt32, ht, rbuf,
                      nullptr, 0u, -1);
        bar_arrive(gctr, 256);                               // b1 = base+1

        prefetch16<2>(rbuf, 0, R2, xrow, g_h2 + rp*HB, g_h1 + wp*HB, bt32);

        window_phase(sm, bw, bx, gctr, 32u*(base+1));
        bar_arrive(gctr, 64);                                // b2 = base+2

        // L2: chunk0 = h2self only; wait(b2) at k0==0 before chunk1 prefetch
        // (b2 >= b1 so h1new rows are covered too).
        lstm_phase<2>(sm, sm + OFF_W2, sm + OFF_BS + 32, sm + OFF_CS + 256, R2,
                      xrow, g_h2 + rp*HB, g_h1 + wp*HB,
                      g_h2 + wp*HB, nullptr, nullptr, bt32, ht, rbuf,
                      gctr, 32u*(base+2), 1);
        bar_arrive(gctr, 256);                               // b3 = base+3

        prefetch16<3>(rbuf, 0, R3, xrow, g_h3 + rp*HB, g_h2 + wp*HB, bt32);

        // L3: chunk0 = h3self only; wait(b3) at k0==0 before chunk1 prefetch
        // (covers w via b3 >= b2).
        lstm_phase<3>(sm, sm + OFF_W3, sm + OFF_BS + 64, sm + OFF_CS + 512, R3,
                      xrow, g_h3 + rp*HB, g_h2 + wp*HB,
                      g_h3 + wp*HB, nullptr, g_out + (size_t)t*HH*BB, bt32, ht, rbuf,
                      gctr, 32u*(base+3), 1);
        // h3 stores released by next step's b1 arrival; h3(t) reads at t+1
        // occur after waits >= b1(t+1).

        rp = wp;
        xrow += 3*BB;
        if (t + 1 < TT)
            prefetch16<1>(rbuf, 0, R1, xrow, g_h1 + rp*HB, nullptr, bt32);
    }
}

__global__ void __launch_bounds__(256) heads_kernel(
    const float* __restrict__ We, const float* __restrict__ be,
    const float* __restrict__ Wpi, const float* __restrict__ bpi,
    const float* __restrict__ Wmu1, const float* __restrict__ bmu1,
    const float* __restrict__ Wmu2, const float* __restrict__ bmu2,
    const float* __restrict__ Ws1, const float* __restrict__ bs1,
    const float* __restrict__ Ws2, const float* __restrict__ bs2,
    const float* __restrict__ Wrho, const float* __restrict__ brho,
    float* __restrict__ dout)
{
    extern __shared__ float ws[];
    const int tid = threadIdx.x;
    const int t = blockIdx.x;

    for (int idx = tid; idx < 256*128; idx += 256){
        int k = idx >> 7, j = idx & 127;
        float v = 0.f;
        if (j == 0)       v = We[k];
        else if (j < 21)  v = Wpi [k*20 + j-1];
        else if (j < 41)  v = Wmu1[k*20 + j-21];
        else if (j < 61)  v = Wmu2[k*20 + j-41];
        else if (j < 81)  v = Ws1 [k*20 + j-61];
        else if (j < 101) v = Ws2 [k*20 + j-81];
        else if (j < 121) v = Wrho[k*20 + j-101];
        ws[idx] = v;
    }
    __syncthreads();

    const int bg = tid & 31, jg = tid >> 5;
    const float* hsrc = g_out + (size_t)t*HH*BB;
    float acc[64];
    #pragma unroll
    for (int i = 0; i < 64; i++) acc[i] = 0.f;

    for (int k = 0; k < 256; k++){
        float4 hv = *(const float4*)(hsrc + k*128 + bg*4);
        #pragma unroll
        for (int jj = 0; jj < 16; jj += 4){
            float4 wv = *(const float4*)(ws + k*128 + jg*16 + jj);
            acc[(jj+0)*4+0] = fmaf(hv.x, wv.x, acc[(jj+0)*4+0]);
            acc[(jj+0)*4+1] = fmaf(hv.y, wv.x, acc[(jj+0)*4+1]);
            acc[(jj+0)*4+2] = fmaf(hv.z, wv.x, acc[(jj+0)*4+2]);
            acc[(jj+0)*4+3] = fmaf(hv.w, wv.x, acc[(jj+0)*4+3]);
            acc[(jj+1)*4+0] = fmaf(hv.x, wv.y, acc[(jj+1)*4+0]);
            acc[(jj+1)*4+1] = fmaf(hv.y, wv.y, acc[(jj+1)*4+1]);
            acc[(jj+1)*4+2] = fmaf(hv.z, wv.y, acc[(jj+1)*4+2]);
            acc[(jj+1)*4+3] = fmaf(hv.w, wv.y, acc[(jj+1)*4+3]);
            acc[(jj+2)*4+0] = fmaf(hv.x, wv.z, acc[(jj+2)*4+0]);
            acc[(jj+2)*4+1] = fmaf(hv.y, wv.z, acc[(jj+2)*4+1]);
            acc[(jj+2)*4+2] = fmaf(hv.z, wv.z, acc[(jj+2)*4+2]);
            acc[(jj+2)*4+3] = fmaf(hv.w, wv.z, acc[(jj+2)*4+3]);
            acc[(jj+3)*4+0] = fmaf(hv.x, wv.w, acc[(jj+3)*4+0]);
            acc[(jj+3)*4+1] = fmaf(hv.y, wv.w, acc[(jj+3)*4+1]);
            acc[(jj+3)*4+2] = fmaf(hv.z, wv.w, acc[(jj+3)*4+2]);
            acc[(jj+3)*4+3] = fmaf(hv.w, wv.w, acc[(jj+3)*4+3]);
        }
    }
    __syncthreads();
    #pragma unroll
    for (int jj = 0; jj < 16; jj++)
        #pragma unroll
        for (int bb = 0; bb < 4; bb++)
            ws[(jg*16 + jj)*128 + bg*4 + bb] = acc[jj*4 + bb];
    __syncthreads();

    if (tid < 128){
        const int b = tid;
        const int tb = t*128 + b;
        float ve = ws[b] + be[0];
        dout[OUT_ES + tb] = 1.0f/(1.0f + __expf(ve));
        float pv[20]; float m = -1e30f;
        #pragma unroll
        for (int g = 0; g < 20; g++){
            pv[g] = ws[(1+g)*128 + b] + bpi[g];
            m = fmaxf(m, pv[g]);
        }
        float s = 0.f;
        #pragma unroll
        for (int g = 0; g < 20; g++){ pv[g] = __expf(pv[g] - m); s += pv[g]; }
        float inv = 1.0f/s;
        #pragma unroll
        for (int g = 0; g < 20; g++){
            dout[OUT_PI + tb*20 + g] = pv[g]*inv;
            dout[OUT_M1 + tb*20 + g] = ws[(21+g) *128 + b] + bmu1[g];
            dout[OUT_M2 + tb*20 + g] = ws[(41+g) *128 + b] + bmu2[g];
            dout[OUT_S1 + tb*20 + g] = __expf(ws[(61+g)*128 + b] + bs1[g]);
            dout[OUT_S2 + tb*20 + g] = __expf(ws[(81+g)*128 + b] + bs2[g]);
            dout[OUT_RH + tb*20 + g] = tanhf(ws[(101+g)*128 + b] + brho[g]);
        }
    }
}

__global__ void cleanup_kernel(){
    if (threadIdx.x < 160) g_ctr[threadIdx.x] = 0u;
}

extern "C" void kernel_launch(void* const* d_in, const int* in_sizes, int n_in,
                              void* d_out, int out_size){
    const float* x    = (const float*)d_in[0];
    const int*   c    = (const int*)  d_in[1];
    const float* Wih1 = (const float*)d_in[2];
    const float* Whh1 = (const float*)d_in[3];
    const float* bih1 = (const float*)d_in[4];
    const float* bhh1 = (const float*)d_in[5];
    const float* Wih2 = (const float*)d_in[6];
    const float* Whh2 = (const float*)d_in[7];
    const float* bih2 = (const float*)d_in[8];
    const float* bhh2 = (const float*)d_in[9];
    const float* Wih3 = (const float*)d_in[10];
    const float* Whh3 = (const float*)d_in[11];
    const float* bih3 = (const float*)d_in[12];
    const float* bhh3 = (const float*)d_in[13];
    const float* Ww   = (const float*)d_in[14];
    const float* bw   = (const float*)d_in[15];
    const float* We   = (const float*)d_in[16];
    const float* be   = (const float*)d_in[17];
    const float* Wpi  = (const float*)d_in[18];
    const float* bpi  = (const float*)d_in[19];
    const float* Wmu1 = (const float*)d_in[20];
    const float* bmu1 = (const float*)d_in[21];
    const float* Wmu2 = (const float*)d_in[22];
    const float* bmu2 = (const float*)d_in[23];
    const float* Ws1  = (const float*)d_in[24];
    const float* bs1  = (const float*)d_in[25];
    const float* Ws2  = (const float*)d_in[26];
    const float* bs2  = (const float*)d_in[27];
    const float* Wrho = (const float*)d_in[28];
    const float* brho = (const float*)d_in[29];
    float* dout = (float*)d_out;

    cudaFuncSetAttribute(recurrent_kernel,
        cudaFuncAttributeMaxDynamicSharedMemorySize, SMEM_BYTES);
    cudaFuncSetAttribute(heads_kernel,
        cudaFuncAttributeMaxDynamicSharedMemorySize, HEADS_BYTES);

    recurrent_kernel<<<NCTA, NTHR, SMEM_BYTES>>>(
        x, c, Wih1, Whh1, bih1, bhh1, Wih2, Whh2, bih2, bhh2,
        Wih3, Whh3, bih3, bhh3, Ww, bw);
    heads_kernel<<<TT, 256, HEADS_BYTES>>>(
        We, be, Wpi, bpi, Wmu1, bmu1, Wmu2, bmu2,
        Ws1, bs1, Ws2, bs2, Wrho, brho, dout);
    cleanup_kernel<<<1, 160>>>();
}